// round 1
// baseline (speedup 1.0000x reference)
#include <cuda_runtime.h>

#define N_TOK 4096
#define DIM   768
#define NEXP  8
#define HID   7680
#define ODIM  768

#define BM 64
#define BN 64
#define BK 16

// ---------------- device scratch (no allocations allowed) ----------------
__device__ float g_hbuf[(size_t)N_TOK * HID];   // packed relu(xW1+b1), 126 MB
__device__ float g_gate[N_TOK];
__device__ int   g_gidx[N_TOK];
__device__ int   g_counts[NEXP];
__device__ int   g_offsets[NEXP + 1];
__device__ int   g_cursor[NEXP];
__device__ int   g_perm[N_TOK];                 // tokens sorted by expert

// ---------------- 0: reset counters (graph replays need this) ------------
__global__ void zero_counts_kernel() {
    if (threadIdx.x < NEXP) g_counts[threadIdx.x] = 0;
}

// ---------------- 1: gating, one warp per token ---------------------------
__global__ void gate_kernel(const float* __restrict__ x,
                            const float* __restrict__ Wg,
                            const float* __restrict__ bg) {
    int gwarp = (blockIdx.x * blockDim.x + threadIdx.x) >> 5;
    int lane  = threadIdx.x & 31;
    if (gwarp >= N_TOK) return;
    const float* xr = x + (size_t)gwarp * DIM;

    float acc[NEXP];
#pragma unroll
    for (int e = 0; e < NEXP; e++) acc[e] = 0.f;

    for (int d = lane; d < DIM; d += 32) {
        float xv = xr[d];
        const float* wr = Wg + d * NEXP;
#pragma unroll
        for (int e = 0; e < NEXP; e++) acc[e] += xv * wr[e];
    }
#pragma unroll
    for (int e = 0; e < NEXP; e++) {
#pragma unroll
        for (int off = 16; off > 0; off >>= 1)
            acc[e] += __shfl_xor_sync(0xffffffffu, acc[e], off);
    }
    if (lane == 0) {
        float lmax = -1e30f; int imax = 0;
#pragma unroll
        for (int e = 0; e < NEXP; e++) {
            float l = acc[e] + bg[e];
            acc[e] = l;
            if (l > lmax) { lmax = l; imax = e; }   // strict > => first max, matches top_k
        }
        float s = 0.f;
#pragma unroll
        for (int e = 0; e < NEXP; e++) s += expf(acc[e] - lmax);
        g_gate[gwarp] = 1.f / s;    // = softmax value at argmax
        g_gidx[gwarp] = imax;
        atomicAdd(&g_counts[imax], 1);
    }
}

// ---------------- 2: exclusive prefix over 8 experts ----------------------
__global__ void prefix_kernel() {
    int s = 0;
    g_offsets[0] = 0;
    for (int e = 0; e < NEXP; e++) {
        g_cursor[e] = s;
        s += g_counts[e];
        g_offsets[e + 1] = s;
    }
}

// ---------------- 3: scatter token ids into per-expert segments ----------
__global__ void scatter_kernel() {
    int n = blockIdx.x * blockDim.x + threadIdx.x;
    if (n >= N_TOK) return;
    int e = g_gidx[n];
    int pos = atomicAdd(&g_cursor[e], 1);
    g_perm[pos] = n;
}

// ---------------- 4: GEMM1  h = relu(x_g @ W1[e] + b1[e]) ----------------
// grid: (HID/BN, N_TOK/BM, NEXP), block 256 (tx 0..15 -> N, ty 0..15 -> M)
__global__ __launch_bounds__(256, 4)
void gemm1_kernel(const float* __restrict__ x,
                  const float* __restrict__ W1,
                  const float* __restrict__ b1) {
    int e   = blockIdx.z;
    int off = g_offsets[e];
    int ne  = g_offsets[e + 1] - off;
    int row0 = blockIdx.y * BM;
    if (row0 >= ne) return;
    int col0 = blockIdx.x * BN;

    __shared__ float As[BK][BM + 4];
    __shared__ float Bs[BK][BN];

    int t  = threadIdx.x;
    int tx = t & 15, ty = t >> 4;

    // A-load mapping: thread loads float4 of x for (row ar, k-cols ac..ac+3)
    int ar = t >> 2;
    int ac = (t & 3) * 4;
    bool arow_ok = (row0 + ar) < ne;
    const float* aptr = nullptr;
    if (arow_ok) {
        int tok = g_perm[off + row0 + ar];
        aptr = x + (size_t)tok * DIM + ac;
    }
    // B-load mapping
    int br = t >> 4;
    int bc = (t & 15) * 4;
    const float* bptr = W1 + (size_t)e * DIM * HID + (size_t)br * HID + col0 + bc;

    float acc[4][4];
#pragma unroll
    for (int i = 0; i < 4; i++)
#pragma unroll
        for (int j = 0; j < 4; j++) acc[i][j] = 0.f;

    for (int k0 = 0; k0 < DIM; k0 += BK) {
        float4 av = arow_ok ? *(const float4*)(aptr + k0)
                            : make_float4(0.f, 0.f, 0.f, 0.f);
        As[ac + 0][ar] = av.x; As[ac + 1][ar] = av.y;
        As[ac + 2][ar] = av.z; As[ac + 3][ar] = av.w;
        *(float4*)&Bs[br][bc] = *(const float4*)(bptr + (size_t)k0 * HID);
        __syncthreads();
#pragma unroll
        for (int k = 0; k < BK; k++) {
            float4 a4 = *(const float4*)&As[k][ty * 4];
            float4 b4 = *(const float4*)&Bs[k][tx * 4];
            float a[4] = {a4.x, a4.y, a4.z, a4.w};
            float b[4] = {b4.x, b4.y, b4.z, b4.w};
#pragma unroll
            for (int i = 0; i < 4; i++)
#pragma unroll
                for (int j = 0; j < 4; j++) acc[i][j] += a[i] * b[j];
        }
        __syncthreads();
    }

    float4 bias = *(const float4*)(b1 + (size_t)e * HID + col0 + tx * 4);
#pragma unroll
    for (int i = 0; i < 4; i++) {
        int r = row0 + ty * 4 + i;
        if (r < ne) {
            float4 o;
            o.x = fmaxf(acc[i][0] + bias.x, 0.f);
            o.y = fmaxf(acc[i][1] + bias.y, 0.f);
            o.z = fmaxf(acc[i][2] + bias.z, 0.f);
            o.w = fmaxf(acc[i][3] + bias.w, 0.f);
            *(float4*)&g_hbuf[(size_t)(off + r) * HID + col0 + tx * 4] = o;
        }
    }
}

// ---------------- 5: GEMM2  out[tok] = gate * (h @ W2[e] + b2[e]) --------
// grid: (ODIM/BN, N_TOK/BM, NEXP)
__global__ __launch_bounds__(256, 4)
void gemm2_kernel(const float* __restrict__ W2,
                  const float* __restrict__ b2,
                  float* __restrict__ out) {
    int e   = blockIdx.z;
    int off = g_offsets[e];
    int ne  = g_offsets[e + 1] - off;
    int row0 = blockIdx.y * BM;
    if (row0 >= ne) return;
    int col0 = blockIdx.x * BN;

    __shared__ float As[BK][BM + 4];
    __shared__ float Bs[BK][BN];

    int t  = threadIdx.x;
    int tx = t & 15, ty = t >> 4;

    int ar = t >> 2;
    int ac = (t & 3) * 4;
    bool arow_ok = (row0 + ar) < ne;
    const float* aptr = g_hbuf + (size_t)(off + row0 + ar) * HID + ac;

    int br = t >> 4;
    int bc = (t & 15) * 4;
    const float* bptr = W2 + (size_t)e * HID * ODIM + (size_t)br * ODIM + col0 + bc;

    float acc[4][4];
#pragma unroll
    for (int i = 0; i < 4; i++)
#pragma unroll
        for (int j = 0; j < 4; j++) acc[i][j] = 0.f;

    for (int k0 = 0; k0 < HID; k0 += BK) {
        float4 av = arow_ok ? *(const float4*)(aptr + k0)
                            : make_float4(0.f, 0.f, 0.f, 0.f);
        As[ac + 0][ar] = av.x; As[ac + 1][ar] = av.y;
        As[ac + 2][ar] = av.z; As[ac + 3][ar] = av.w;
        *(float4*)&Bs[br][bc] = *(const float4*)(bptr + (size_t)k0 * ODIM);
        __syncthreads();
#pragma unroll
        for (int k = 0; k < BK; k++) {
            float4 a4 = *(const float4*)&As[k][ty * 4];
            float4 b4 = *(const float4*)&Bs[k][tx * 4];
            float a[4] = {a4.x, a4.y, a4.z, a4.w};
            float b[4] = {b4.x, b4.y, b4.z, b4.w};
#pragma unroll
            for (int i = 0; i < 4; i++)
#pragma unroll
                for (int j = 0; j < 4; j++) acc[i][j] += a[i] * b[j];
        }
        __syncthreads();
    }

    float4 bias = *(const float4*)(b2 + (size_t)e * ODIM + col0 + tx * 4);
#pragma unroll
    for (int i = 0; i < 4; i++) {
        int r = row0 + ty * 4 + i;
        if (r < ne) {
            int tok = g_perm[off + r];
            float g = g_gate[tok];
            float4 o;
            o.x = g * (acc[i][0] + bias.x);
            o.y = g * (acc[i][1] + bias.y);
            o.z = g * (acc[i][2] + bias.z);
            o.w = g * (acc[i][3] + bias.w);
            *(float4*)&out[(size_t)tok * ODIM + col0 + tx * 4] = o;
        }
    }
}

// ---------------- launch ---------------------------------------------------
extern "C" void kernel_launch(void* const* d_in, const int* in_sizes, int n_in,
                              void* d_out, int out_size) {
    const float* x  = (const float*)d_in[0];
    const float* Wg = (const float*)d_in[1];
    const float* bg = (const float*)d_in[2];
    const float* W1 = (const float*)d_in[3];
    const float* b1 = (const float*)d_in[4];
    const float* W2 = (const float*)d_in[5];
    const float* b2 = (const float*)d_in[6];
    float* out = (float*)d_out;

    zero_counts_kernel<<<1, 32>>>();
    gate_kernel<<<(N_TOK * 32 + 255) / 256, 256>>>(x, Wg, bg);
    prefix_kernel<<<1, 1>>>();
    scatter_kernel<<<(N_TOK + 255) / 256, 256>>>();

    dim3 g1(HID / BN, N_TOK / BM, NEXP);
    gemm1_kernel<<<g1, 256>>>(x, W1, b1);

    dim3 g2(ODIM / BN, N_TOK / BM, NEXP);
    gemm2_kernel<<<g2, 256>>>(W2, b2, out);
}

// round 2
// speedup vs baseline: 2.7630x; 2.7630x over previous
#include <cuda_runtime.h>

#define N_TOK 4096
#define DIM   768
#define NEXP  8
#define HID   7680
#define ODIM  768

#define BM 128
#define BN 64
#define BK 32
#define LDA 36   // BK + 4  (conflict-free for A fragment reads, 16B-aligned rows)
#define LDB 72   // BN + 8  (conflict-free for B fragment reads, 16B-aligned rows)

// ---------------- device scratch ----------------
__device__ float g_hbuf[(size_t)N_TOK * HID];   // packed relu(xW1+b1)
__device__ float g_gate[N_TOK];
__device__ int   g_gidx[N_TOK];
__device__ int   g_counts[NEXP];
__device__ int   g_offsets[NEXP + 1];
__device__ int   g_cursor[NEXP];
__device__ int   g_perm[N_TOK];

// ---------------- helpers ----------------
__device__ __forceinline__ unsigned f2tf32(float f) {
    unsigned r;
    asm("cvt.rna.tf32.f32 %0, %1;" : "=r"(r) : "f"(f));
    return r;
}

__device__ __forceinline__ void mma_tf32(float c[4], const unsigned a[4], const unsigned b[2]) {
    asm volatile(
        "mma.sync.aligned.m16n8k8.row.col.f32.tf32.tf32.f32 "
        "{%0,%1,%2,%3}, {%4,%5,%6,%7}, {%8,%9}, {%0,%1,%2,%3};"
        : "+f"(c[0]), "+f"(c[1]), "+f"(c[2]), "+f"(c[3])
        : "r"(a[0]), "r"(a[1]), "r"(a[2]), "r"(a[3]), "r"(b[0]), "r"(b[1]));
}

// ---------------- prologue kernels ----------------
__global__ void zero_counts_kernel() {
    if (threadIdx.x < NEXP) g_counts[threadIdx.x] = 0;
}

__global__ void gate_kernel(const float* __restrict__ x,
                            const float* __restrict__ Wg,
                            const float* __restrict__ bg) {
    int gwarp = (blockIdx.x * blockDim.x + threadIdx.x) >> 5;
    int lane  = threadIdx.x & 31;
    if (gwarp >= N_TOK) return;
    const float* xr = x + (size_t)gwarp * DIM;

    float acc[NEXP];
#pragma unroll
    for (int e = 0; e < NEXP; e++) acc[e] = 0.f;
    for (int d = lane; d < DIM; d += 32) {
        float xv = xr[d];
        const float* wr = Wg + d * NEXP;
#pragma unroll
        for (int e = 0; e < NEXP; e++) acc[e] += xv * wr[e];
    }
#pragma unroll
    for (int e = 0; e < NEXP; e++)
#pragma unroll
        for (int off = 16; off > 0; off >>= 1)
            acc[e] += __shfl_xor_sync(0xffffffffu, acc[e], off);
    if (lane == 0) {
        float lmax = -1e30f; int imax = 0;
#pragma unroll
        for (int e = 0; e < NEXP; e++) {
            float l = acc[e] + bg[e];
            acc[e] = l;
            if (l > lmax) { lmax = l; imax = e; }
        }
        float s = 0.f;
#pragma unroll
        for (int e = 0; e < NEXP; e++) s += expf(acc[e] - lmax);
        g_gate[gwarp] = 1.f / s;
        g_gidx[gwarp] = imax;
        atomicAdd(&g_counts[imax], 1);
    }
}

__global__ void prefix_kernel() {
    int s = 0;
    g_offsets[0] = 0;
    for (int e = 0; e < NEXP; e++) {
        g_cursor[e] = s;
        s += g_counts[e];
        g_offsets[e + 1] = s;
    }
}

__global__ void scatter_kernel() {
    int n = blockIdx.x * blockDim.x + threadIdx.x;
    if (n >= N_TOK) return;
    int e = g_gidx[n];
    int pos = atomicAdd(&g_cursor[e], 1);
    g_perm[pos] = n;
}

// ---------------- GEMM1: h = relu(x_g @ W1[e] + b1[e]) -------------------
// grid (HID/BN, N_TOK/BM, NEXP), block 256
__global__ __launch_bounds__(256, 2)
void gemm1_kernel(const float* __restrict__ x,
                  const float* __restrict__ W1,
                  const float* __restrict__ b1) {
    int e    = blockIdx.z;
    int off  = g_offsets[e];
    int ne   = g_offsets[e + 1] - off;
    int row0 = blockIdx.y * BM;
    if (row0 >= ne) return;
    int col0 = blockIdx.x * BN;

    __shared__ unsigned As[BM * LDA];
    __shared__ unsigned Bs[BK * LDB];
    __shared__ int      s_tok[BM];

    int t    = threadIdx.x;
    int lane = t & 31;
    int wid  = t >> 5;
    int gr   = lane >> 2;       // group row 0..7
    int tg   = lane & 3;        // thread-in-group 0..3
    int wm   = (wid & 3) * 32;  // warp m offset
    int wn   = (wid >> 2) * 32; // warp n offset

    if (t < BM) {
        int r = row0 + t;
        s_tok[t] = (r < ne) ? g_perm[off + r] : -1;
    }
    __syncthreads();

    // A gmem mapping: 4 rows/thread, 1 float4/row/iter
    int arl = t >> 3;           // 0..31
    int ac4 = (t & 7) * 4;      // k-col within tile
    const float* arow[4];
    bool aok[4];
#pragma unroll
    for (int i = 0; i < 4; i++) {
        int rl = arl + i * 32;
        int tok = s_tok[rl];
        aok[i]  = (tok >= 0);
        arow[i] = aok[i] ? (x + (size_t)tok * DIM + ac4) : x;
    }
    // B gmem mapping: 2 rows/thread, 1 float4/row/iter
    int bkr = t >> 4;           // 0..15
    int bc4 = (t & 15) * 4;
    const float* bbase = W1 + (size_t)e * DIM * HID + col0 + bc4;

    float4 aReg[4], bReg[2];
    auto load_g = [&](int k0) {
#pragma unroll
        for (int i = 0; i < 4; i++)
            aReg[i] = aok[i] ? *(const float4*)(arow[i] + k0)
                             : make_float4(0.f, 0.f, 0.f, 0.f);
#pragma unroll
        for (int i = 0; i < 2; i++)
            bReg[i] = *(const float4*)(bbase + (size_t)(k0 + bkr + i * 16) * HID);
    };
    auto store_s = [&]() {
#pragma unroll
        for (int i = 0; i < 4; i++) {
            unsigned* p = &As[(arl + i * 32) * LDA + ac4];
            p[0] = f2tf32(aReg[i].x); p[1] = f2tf32(aReg[i].y);
            p[2] = f2tf32(aReg[i].z); p[3] = f2tf32(aReg[i].w);
        }
#pragma unroll
        for (int i = 0; i < 2; i++) {
            unsigned* p = &Bs[(bkr + i * 16) * LDB + bc4];
            p[0] = f2tf32(bReg[i].x); p[1] = f2tf32(bReg[i].y);
            p[2] = f2tf32(bReg[i].z); p[3] = f2tf32(bReg[i].w);
        }
    };

    float acc[2][4][4];
#pragma unroll
    for (int mt = 0; mt < 2; mt++)
#pragma unroll
        for (int nt = 0; nt < 4; nt++)
#pragma unroll
            for (int i = 0; i < 4; i++) acc[mt][nt][i] = 0.f;

    const int NIT = DIM / BK;
    load_g(0);
    store_s();
    __syncthreads();

    for (int it = 0; it < NIT; it++) {
        if (it + 1 < NIT) load_g((it + 1) * BK);
#pragma unroll
        for (int ks = 0; ks < BK / 8; ks++) {
            unsigned a[2][4], b[4][2];
#pragma unroll
            for (int mt = 0; mt < 2; mt++) {
                int r = wm + mt * 16 + gr;
                a[mt][0] = As[r * LDA + ks * 8 + tg];
                a[mt][1] = As[(r + 8) * LDA + ks * 8 + tg];
                a[mt][2] = As[r * LDA + ks * 8 + tg + 4];
                a[mt][3] = As[(r + 8) * LDA + ks * 8 + tg + 4];
            }
#pragma unroll
            for (int nt = 0; nt < 4; nt++) {
                int c = wn + nt * 8 + gr;
                b[nt][0] = Bs[(ks * 8 + tg) * LDB + c];
                b[nt][1] = Bs[(ks * 8 + tg + 4) * LDB + c];
            }
#pragma unroll
            for (int mt = 0; mt < 2; mt++)
#pragma unroll
                for (int nt = 0; nt < 4; nt++)
                    mma_tf32(acc[mt][nt], a[mt], b[nt]);
        }
        if (it + 1 < NIT) {
            __syncthreads();
            store_s();
            __syncthreads();
        }
    }

    // epilogue: bias + relu -> g_hbuf (packed rows)
#pragma unroll
    for (int mt = 0; mt < 2; mt++) {
        int rl0 = wm + mt * 16 + gr;
#pragma unroll
        for (int nt = 0; nt < 4; nt++) {
            int col = col0 + wn + nt * 8 + tg * 2;
            float b0 = b1[(size_t)e * HID + col];
            float b1v = b1[(size_t)e * HID + col + 1];
            if (row0 + rl0 < ne) {
                float2 o;
                o.x = fmaxf(acc[mt][nt][0] + b0, 0.f);
                o.y = fmaxf(acc[mt][nt][1] + b1v, 0.f);
                *(float2*)&g_hbuf[(size_t)(off + row0 + rl0) * HID + col] = o;
            }
            if (row0 + rl0 + 8 < ne) {
                float2 o;
                o.x = fmaxf(acc[mt][nt][2] + b0, 0.f);
                o.y = fmaxf(acc[mt][nt][3] + b1v, 0.f);
                *(float2*)&g_hbuf[(size_t)(off + row0 + rl0 + 8) * HID + col] = o;
            }
        }
    }
}

// ---------------- GEMM2: out[tok] = gate * (h @ W2[e] + b2[e]) ------------
// grid (ODIM/BN, N_TOK/BM, NEXP), block 256
__global__ __launch_bounds__(256, 2)
void gemm2_kernel(const float* __restrict__ W2,
                  const float* __restrict__ b2,
                  float* __restrict__ out) {
    int e    = blockIdx.z;
    int off  = g_offsets[e];
    int ne   = g_offsets[e + 1] - off;
    int row0 = blockIdx.y * BM;
    if (row0 >= ne) return;
    int col0 = blockIdx.x * BN;

    __shared__ unsigned As[BM * LDA];
    __shared__ unsigned Bs[BK * LDB];
    __shared__ int      s_tok[BM];

    int t    = threadIdx.x;
    int lane = t & 31;
    int wid  = t >> 5;
    int gr   = lane >> 2;
    int tg   = lane & 3;
    int wm   = (wid & 3) * 32;
    int wn   = (wid >> 2) * 32;

    if (t < BM) {
        int r = row0 + t;
        s_tok[t] = (r < ne) ? g_perm[off + r] : -1;
    }
    __syncthreads();

    int arl = t >> 3;
    int ac4 = (t & 7) * 4;
    const float* arow[4];
    bool aok[4];
#pragma unroll
    for (int i = 0; i < 4; i++) {
        int rl = arl + i * 32;
        aok[i]  = (row0 + rl < ne);
        arow[i] = g_hbuf + (size_t)(off + row0 + rl) * HID + ac4;
    }
    int bkr = t >> 4;
    int bc4 = (t & 15) * 4;
    const float* bbase = W2 + (size_t)e * HID * ODIM + col0 + bc4;

    float4 aReg[4], bReg[2];
    auto load_g = [&](int k0) {
#pragma unroll
        for (int i = 0; i < 4; i++)
            aReg[i] = aok[i] ? *(const float4*)(arow[i] + k0)
                             : make_float4(0.f, 0.f, 0.f, 0.f);
#pragma unroll
        for (int i = 0; i < 2; i++)
            bReg[i] = *(const float4*)(bbase + (size_t)(k0 + bkr + i * 16) * ODIM);
    };
    auto store_s = [&]() {
#pragma unroll
        for (int i = 0; i < 4; i++) {
            unsigned* p = &As[(arl + i * 32) * LDA + ac4];
            p[0] = f2tf32(aReg[i].x); p[1] = f2tf32(aReg[i].y);
            p[2] = f2tf32(aReg[i].z); p[3] = f2tf32(aReg[i].w);
        }
#pragma unroll
        for (int i = 0; i < 2; i++) {
            unsigned* p = &Bs[(bkr + i * 16) * LDB + bc4];
            p[0] = f2tf32(bReg[i].x); p[1] = f2tf32(bReg[i].y);
            p[2] = f2tf32(bReg[i].z); p[3] = f2tf32(bReg[i].w);
        }
    };

    float acc[2][4][4];
#pragma unroll
    for (int mt = 0; mt < 2; mt++)
#pragma unroll
        for (int nt = 0; nt < 4; nt++)
#pragma unroll
            for (int i = 0; i < 4; i++) acc[mt][nt][i] = 0.f;

    const int NIT = HID / BK;
    load_g(0);
    store_s();
    __syncthreads();

    for (int it = 0; it < NIT; it++) {
        if (it + 1 < NIT) load_g((it + 1) * BK);
#pragma unroll
        for (int ks = 0; ks < BK / 8; ks++) {
            unsigned a[2][4], b[4][2];
#pragma unroll
            for (int mt = 0; mt < 2; mt++) {
                int r = wm + mt * 16 + gr;
                a[mt][0] = As[r * LDA + ks * 8 + tg];
                a[mt][1] = As[(r + 8) * LDA + ks * 8 + tg];
                a[mt][2] = As[r * LDA + ks * 8 + tg + 4];
                a[mt][3] = As[(r + 8) * LDA + ks * 8 + tg + 4];
            }
#pragma unroll
            for (int nt = 0; nt < 4; nt++) {
                int c = wn + nt * 8 + gr;
                b[nt][0] = Bs[(ks * 8 + tg) * LDB + c];
                b[nt][1] = Bs[(ks * 8 + tg + 4) * LDB + c];
            }
#pragma unroll
            for (int mt = 0; mt < 2; mt++)
#pragma unroll
                for (int nt = 0; nt < 4; nt++)
                    mma_tf32(acc[mt][nt], a[mt], b[nt]);
        }
        if (it + 1 < NIT) {
            __syncthreads();
            store_s();
            __syncthreads();
        }
    }

    // epilogue: bias, gate scale, scatter to out by token id
#pragma unroll
    for (int mt = 0; mt < 2; mt++) {
        int rl0 = wm + mt * 16 + gr;
#pragma unroll
        for (int nt = 0; nt < 4; nt++) {
            int col = col0 + wn + nt * 8 + tg * 2;
            float b0 = b2[(size_t)e * ODIM + col];
            float b1v = b2[(size_t)e * ODIM + col + 1];
            int tok0 = s_tok[rl0];
            if (tok0 >= 0) {
                float g = g_gate[tok0];
                float2 o;
                o.x = g * (acc[mt][nt][0] + b0);
                o.y = g * (acc[mt][nt][1] + b1v);
                *(float2*)&out[(size_t)tok0 * ODIM + col] = o;
            }
            int tok1 = (rl0 + 8 < BM) ? s_tok[rl0 + 8] : -1;
            if (tok1 >= 0) {
                float g = g_gate[tok1];
                float2 o;
                o.x = g * (acc[mt][nt][2] + b0);
                o.y = g * (acc[mt][nt][3] + b1v);
                *(float2*)&out[(size_t)tok1 * ODIM + col] = o;
            }
        }
    }
}

// ---------------- launch ----------------
extern "C" void kernel_launch(void* const* d_in, const int* in_sizes, int n_in,
                              void* d_out, int out_size) {
    const float* x  = (const float*)d_in[0];
    const float* Wg = (const float*)d_in[1];
    const float* bg = (const float*)d_in[2];
    const float* W1 = (const float*)d_in[3];
    const float* b1 = (const float*)d_in[4];
    const float* W2 = (const float*)d_in[5];
    const float* b2 = (const float*)d_in[6];
    float* out = (float*)d_out;

    zero_counts_kernel<<<1, 32>>>();
    gate_kernel<<<(N_TOK * 32 + 255) / 256, 256>>>(x, Wg, bg);
    prefix_kernel<<<1, 1>>>();
    scatter_kernel<<<(N_TOK + 255) / 256, 256>>>();

    dim3 g1(HID / BN, N_TOK / BM, NEXP);
    gemm1_kernel<<<g1, 256>>>(x, W1, b1);

    dim3 g2(ODIM / BN, N_TOK / BM, NEXP);
    gemm2_kernel<<<g2, 256>>>(W2, b2, out);
}

// round 4
// speedup vs baseline: 3.0028x; 1.0868x over previous
#include <cuda_runtime.h>
#include <cstdint>

#define N_TOK 4096
#define DIM   768
#define NEXP  8
#define HID   7680
#define ODIM  768

#define BM 128
#define BK 32
#define LDA 36            // words; conflict-free A fragment reads

// ---------------- device scratch ----------------
__device__ float g_hbuf[(size_t)N_TOK * HID];
__device__ float g_gate[N_TOK];
__device__ int   g_gidx[N_TOK];
__device__ int   g_counts[NEXP];
__device__ int   g_offsets[NEXP + 1];
__device__ int   g_cursor[NEXP];
__device__ int   g_perm[N_TOK];

// ---------------- helpers ----------------
static __device__ __forceinline__ uint32_t smem_u32(const void* p) {
    uint32_t a;
    asm("{ .reg .u64 t; cvta.to.shared.u64 t, %1; cvt.u32.u64 %0, t; }" : "=r"(a) : "l"(p));
    return a;
}
static __device__ __forceinline__ uint32_t f2tf32(float f) {
    uint32_t r; asm("cvt.rna.tf32.f32 %0, %1;" : "=r"(r) : "f"(f)); return r;
}
static __device__ __forceinline__ void mma_tf32(float c[4], const uint32_t a[4],
                                                const uint32_t b[2]) {
    asm volatile(
        "mma.sync.aligned.m16n8k8.row.col.f32.tf32.tf32.f32 "
        "{%0,%1,%2,%3}, {%4,%5,%6,%7}, {%8,%9}, {%0,%1,%2,%3};"
        : "+f"(c[0]), "+f"(c[1]), "+f"(c[2]), "+f"(c[3])
        : "r"(a[0]), "r"(a[1]), "r"(a[2]), "r"(a[3]), "r"(b[0]), "r"(b[1]));
}
static __device__ __forceinline__ void cp16(uint32_t dst, const float* src, uint32_t sz) {
    asm volatile("cp.async.ca.shared.global [%0], [%1], 16, %2;"
                 :: "r"(dst), "l"(src), "r"(sz) : "memory");
}
static __device__ __forceinline__ void cp_commit() {
    asm volatile("cp.async.commit_group;" ::: "memory");
}
static __device__ __forceinline__ void cp_wait0() {
    asm volatile("cp.async.wait_group 0;" ::: "memory");
}

// ---------------- prologue kernels ----------------
__global__ void zero_counts_kernel() {
    if (threadIdx.x < NEXP) g_counts[threadIdx.x] = 0;
}

__global__ void gate_kernel(const float* __restrict__ x,
                            const float* __restrict__ Wg,
                            const float* __restrict__ bg) {
    int gwarp = (blockIdx.x * blockDim.x + threadIdx.x) >> 5;
    int lane  = threadIdx.x & 31;
    if (gwarp >= N_TOK) return;
    const float* xr = x + (size_t)gwarp * DIM;

    float acc[NEXP];
#pragma unroll
    for (int e = 0; e < NEXP; e++) acc[e] = 0.f;
    for (int d = lane; d < DIM; d += 32) {
        float xv = xr[d];
        const float* wr = Wg + d * NEXP;
#pragma unroll
        for (int e = 0; e < NEXP; e++) acc[e] += xv * wr[e];
    }
#pragma unroll
    for (int e = 0; e < NEXP; e++)
#pragma unroll
        for (int off = 16; off > 0; off >>= 1)
            acc[e] += __shfl_xor_sync(0xffffffffu, acc[e], off);
    if (lane == 0) {
        float lmax = -1e30f; int imax = 0;
#pragma unroll
        for (int e = 0; e < NEXP; e++) {
            float l = acc[e] + bg[e];
            acc[e] = l;
            if (l > lmax) { lmax = l; imax = e; }
        }
        float s = 0.f;
#pragma unroll
        for (int e = 0; e < NEXP; e++) s += expf(acc[e] - lmax);
        g_gate[gwarp] = 1.f / s;
        g_gidx[gwarp] = imax;
        atomicAdd(&g_counts[imax], 1);
    }
}

__global__ void prefix_kernel() {
    int s = 0;
    g_offsets[0] = 0;
    for (int e = 0; e < NEXP; e++) {
        g_cursor[e] = s;
        s += g_counts[e];
        g_offsets[e + 1] = s;
    }
}

__global__ void scatter_kernel() {
    int n = blockIdx.x * blockDim.x + threadIdx.x;
    if (n >= N_TOK) return;
    int e = g_gidx[n];
    int pos = atomicAdd(&g_cursor[e], 1);
    g_perm[pos] = n;
}

// ---------------- templated tensor-core GEMM -----------------------------
// G2=false: h = relu(x_g @ W1[e] + b1[e]) -> g_hbuf   (BN=128)
// G2=true : out[tok] = gate * (h @ W2[e] + b2[e])     (BN=64)
// grid (NWALL/BN, N_TOK/BM, NEXP), block 256 (8 warps, 4x2; warp tile 32 x BN/2)
template <int BN, bool G2, int KT, int NWALL>
__global__ __launch_bounds__(256, 2)
void moe_gemm(const float* __restrict__ Asrc,   // x (G1) / ignored (G2 uses g_hbuf)
              const float* __restrict__ W,
              const float* __restrict__ bias,
              float* __restrict__ outp) {
    constexpr int NT  = BN / 16;          // n-subtiles per warp
    constexpr int LDB = BN + 8;           // words
    constexpr int ASB = BM * LDA * 4;     // bytes per A stage
    constexpr int BSB = BK * LDB * 4;     // bytes per B stage
    constexpr int TPR = BN / 4;           // threads per B k-row
    constexpr int RPP = 256 / TPR;        // B k-rows per pass
    constexpr int NB  = BK / RPP;         // B chunks per thread
    constexpr int NIT = KT / BK;

    int e    = blockIdx.z;
    int off  = g_offsets[e];
    int ne   = g_offsets[e + 1] - off;
    int row0 = blockIdx.y * BM;
    if (row0 >= ne) return;
    int col0 = blockIdx.x * BN;

    extern __shared__ char smem[];
    uint32_t sb    = smem_u32(smem);
    int*     s_tok = (int*)smem;          // 128 ints

    int t    = threadIdx.x;
    int lane = t & 31;
    int wid  = t >> 5;
    int gr   = lane >> 2;
    int tg   = lane & 3;
    int wm   = (wid & 3) * 32;
    int wn   = (wid >> 2) * (BN / 2);

    if (t < BM) {
        int r = row0 + t;
        s_tok[t] = (r < ne) ? g_perm[off + r] : -1;
    }
    __syncthreads();

    // A cp.async mapping: m = (t>>3)+32i, chunk c4 = t&7 (16B along K)
    int mA = t >> 3;
    int c4 = t & 7;
    const float* arow[4];
    uint32_t asz[4];
#pragma unroll
    for (int i = 0; i < 4; i++) {
        int m = mA + 32 * i;
        if (!G2) {
            int tok = s_tok[m];
            asz[i]  = (tok >= 0) ? 16u : 0u;
            arow[i] = Asrc + (size_t)(tok >= 0 ? tok : 0) * DIM + c4 * 4;
        } else {
            bool ok = (row0 + m) < ne;
            asz[i]  = ok ? 16u : 0u;
            int ridx = ok ? (off + row0 + m) : 0;
            arow[i] = g_hbuf + (size_t)ridx * (size_t)KT + c4 * 4;
        }
    }
    // B cp.async mapping
    int bk  = t / TPR;
    int bc4 = t % TPR;
    const float* wb = W + (size_t)e * KT * NWALL + col0 + bc4 * 4;

    auto issue = [&](int it) {
        int buf = it & 1;
        uint32_t ab = sb + 512 + buf * ASB;
        uint32_t bb = sb + 512 + 2 * ASB + buf * BSB;
        int k0 = it * BK;
#pragma unroll
        for (int i = 0; i < 4; i++)
            cp16(ab + (uint32_t)((mA + 32 * i) * LDA + c4 * 4) * 4, arow[i] + k0, asz[i]);
#pragma unroll
        for (int i = 0; i < NB; i++)
            cp16(bb + (uint32_t)((bk + RPP * i) * LDB + bc4 * 4) * 4,
                 wb + (size_t)(k0 + bk + RPP * i) * NWALL, 16u);
        cp_commit();
    };

    float acc[2][NT][4];
#pragma unroll
    for (int mt = 0; mt < 2; mt++)
#pragma unroll
        for (int nt = 0; nt < NT; nt++)
#pragma unroll
            for (int i = 0; i < 4; i++) acc[mt][nt][i] = 0.f;

    issue(0);
    for (int it = 0; it < NIT; it++) {
        cp_wait0();
        __syncthreads();
        if (it + 1 < NIT) issue(it + 1);

        int buf = it & 1;
        const float* As = (const float*)(smem + 512 + buf * ASB);
        const float* Bs = (const float*)(smem + 512 + 2 * ASB + buf * BSB);
#pragma unroll
        for (int ks = 0; ks < BK / 8; ks++) {
            uint32_t a[2][4], b[NT][2];
#pragma unroll
            for (int mt = 0; mt < 2; mt++) {
                int r = wm + mt * 16 + gr;
                a[mt][0] = f2tf32(As[r * LDA + ks * 8 + tg]);
                a[mt][1] = f2tf32(As[(r + 8) * LDA + ks * 8 + tg]);
                a[mt][2] = f2tf32(As[r * LDA + ks * 8 + tg + 4]);
                a[mt][3] = f2tf32(As[(r + 8) * LDA + ks * 8 + tg + 4]);
            }
#pragma unroll
            for (int nt = 0; nt < NT; nt++) {
                int c = wn + nt * 8 + gr;
                b[nt][0] = f2tf32(Bs[(ks * 8 + tg) * LDB + c]);
                b[nt][1] = f2tf32(Bs[(ks * 8 + tg + 4) * LDB + c]);
            }
#pragma unroll
            for (int mt = 0; mt < 2; mt++)
#pragma unroll
                for (int nt = 0; nt < NT; nt++)
                    mma_tf32(acc[mt][nt], a[mt], b[nt]);
        }
    }

    // -------- epilogue --------
    const float* be = bias + (size_t)e * NWALL;
#pragma unroll
    for (int mt = 0; mt < 2; mt++) {
        int rl0 = wm + mt * 16 + gr;
#pragma unroll
        for (int half = 0; half < 2; half++) {
            int rl = rl0 + half * 8;
            if (!G2) {
                if (row0 + rl >= ne) continue;
                float* orow = g_hbuf + (size_t)(off + row0 + rl) * NWALL;
#pragma unroll
                for (int nt = 0; nt < NT; nt++) {
                    int col = col0 + wn + nt * 8 + tg * 2;
                    float2 bb = *(const float2*)(be + col);
                    float2 o;
                    o.x = fmaxf(acc[mt][nt][half * 2 + 0] + bb.x, 0.f);
                    o.y = fmaxf(acc[mt][nt][half * 2 + 1] + bb.y, 0.f);
                    *(float2*)(orow + col) = o;
                }
            } else {
                int tok = s_tok[rl];
                if (tok < 0) continue;
                float g = g_gate[tok];
                float* orow = outp + (size_t)tok * NWALL;
#pragma unroll
                for (int nt = 0; nt < NT; nt++) {
                    int col = col0 + wn + nt * 8 + tg * 2;
                    float2 bb = *(const float2*)(be + col);
                    float2 o;
                    o.x = g * (acc[mt][nt][half * 2 + 0] + bb.x);
                    o.y = g * (acc[mt][nt][half * 2 + 1] + bb.y);
                    *(float2*)(orow + col) = o;
                }
            }
        }
    }
}

// smem totals
#define SMEM1 (512 + 2 * (BM * LDA * 4) + 2 * (BK * (128 + 8) * 4))   // 72192
#define SMEM2 (512 + 2 * (BM * LDA * 4) + 2 * (BK * (64 + 8) * 4))    // 55808

// ---------------- launch ----------------
extern "C" void kernel_launch(void* const* d_in, const int* in_sizes, int n_in,
                              void* d_out, int out_size) {
    const float* x  = (const float*)d_in[0];
    const float* Wg = (const float*)d_in[1];
    const float* bg = (const float*)d_in[2];
    const float* W1 = (const float*)d_in[3];
    const float* b1 = (const float*)d_in[4];
    const float* W2 = (const float*)d_in[5];
    const float* b2 = (const float*)d_in[6];
    float* out = (float*)d_out;

    static bool attr_done = false;
    if (!attr_done) {
        cudaFuncSetAttribute((const void*)moe_gemm<128, false, DIM, HID>,
                             cudaFuncAttributeMaxDynamicSharedMemorySize, SMEM1);
        cudaFuncSetAttribute((const void*)moe_gemm<64, true, HID, ODIM>,
                             cudaFuncAttributeMaxDynamicSharedMemorySize, SMEM2);
        attr_done = true;
    }

    zero_counts_kernel<<<1, 32>>>();
    gate_kernel<<<(N_TOK * 32 + 255) / 256, 256>>>(x, Wg, bg);
    prefix_kernel<<<1, 1>>>();
    scatter_kernel<<<(N_TOK + 255) / 256, 256>>>();

    dim3 g1(HID / 128, N_TOK / BM, NEXP);
    moe_gemm<128, false, DIM, HID><<<g1, 256, SMEM1>>>(x, W1, b1, nullptr);

    dim3 g2(ODIM / 64, N_TOK / BM, NEXP);
    moe_gemm<64, true, HID, ODIM><<<g2, 256, SMEM2>>>(nullptr, W2, b2, out);
}

// round 5
// speedup vs baseline: 5.5936x; 1.8628x over previous
#include <cuda_runtime.h>
#include <cuda_fp16.h>
#include <cstdint>

#define N_TOK 4096
#define DIM   768
#define NEXP  8
#define HID   7680
#define ODIM  768

#define BM 128
#define BN 128
#define BK 32

// smem strides (halfs)
#define SA 40      // 32 data + 8 pad -> 80 B rows
#define SB 136     // 128 data + 8 pad -> 272 B rows
#define ASZ (BM * SA * 2)          // 10240 B per A stage
#define BSZ (BK * SB * 2)          // 8704 B per B stage
#define SMEM_TOT (512 + 2 * ASZ + 2 * BSZ)   // 38400 B

// ---------------- device scratch ----------------
__device__ __half g_w1h[(size_t)NEXP * DIM * HID];   // 94.4 MB
__device__ __half g_w2h[(size_t)NEXP * HID * ODIM];  // 94.4 MB
__device__ __half g_xh[(size_t)N_TOK * DIM];         // 6.3 MB
__device__ __half g_hbufh[(size_t)N_TOK * HID];      // 63 MB (packed)
__device__ float g_gate[N_TOK];
__device__ int   g_gidx[N_TOK];
__device__ int   g_counts[NEXP];
__device__ int   g_offsets[NEXP + 1];
__device__ int   g_cursor[NEXP];
__device__ int   g_perm[N_TOK];

// ---------------- helpers ----------------
static __device__ __forceinline__ uint32_t smem_u32(const void* p) {
    uint32_t a;
    asm("{ .reg .u64 t; cvta.to.shared.u64 t, %1; cvt.u32.u64 %0, t; }" : "=r"(a) : "l"(p));
    return a;
}
static __device__ __forceinline__ void cp16(uint32_t dst, const void* src, uint32_t sz) {
    asm volatile("cp.async.ca.shared.global [%0], [%1], 16, %2;"
                 :: "r"(dst), "l"(src), "r"(sz) : "memory");
}
static __device__ __forceinline__ void cp_commit() {
    asm volatile("cp.async.commit_group;" ::: "memory");
}
static __device__ __forceinline__ void cp_wait0() {
    asm volatile("cp.async.wait_group 0;" ::: "memory");
}
static __device__ __forceinline__ void ldsm4(uint32_t& r0, uint32_t& r1, uint32_t& r2,
                                             uint32_t& r3, uint32_t a) {
    asm volatile("ldmatrix.sync.aligned.m8n8.x4.shared.b16 {%0,%1,%2,%3}, [%4];"
                 : "=r"(r0), "=r"(r1), "=r"(r2), "=r"(r3) : "r"(a));
}
static __device__ __forceinline__ void ldsm4t(uint32_t& r0, uint32_t& r1, uint32_t& r2,
                                              uint32_t& r3, uint32_t a) {
    asm volatile("ldmatrix.sync.aligned.m8n8.x4.trans.shared.b16 {%0,%1,%2,%3}, [%4];"
                 : "=r"(r0), "=r"(r1), "=r"(r2), "=r"(r3) : "r"(a));
}
static __device__ __forceinline__ void mma_f16(float c[4], uint32_t a0, uint32_t a1,
                                               uint32_t a2, uint32_t a3,
                                               uint32_t b0, uint32_t b1) {
    asm volatile(
        "mma.sync.aligned.m16n8k16.row.col.f32.f16.f16.f32 "
        "{%0,%1,%2,%3}, {%4,%5,%6,%7}, {%8,%9}, {%0,%1,%2,%3};"
        : "+f"(c[0]), "+f"(c[1]), "+f"(c[2]), "+f"(c[3])
        : "r"(a0), "r"(a1), "r"(a2), "r"(a3), "r"(b0), "r"(b1));
}

// ---------------- fp32 -> fp16 conversion (8 floats/thread) ----------------
__global__ void f32_to_f16_kernel(const float4* __restrict__ src,
                                  uint4* __restrict__ dst, int n8) {
    int i = blockIdx.x * blockDim.x + threadIdx.x;
    if (i >= n8) return;
    float4 v0 = src[2 * i], v1 = src[2 * i + 1];
    __half2 h0 = __floats2half2_rn(v0.x, v0.y);
    __half2 h1 = __floats2half2_rn(v0.z, v0.w);
    __half2 h2 = __floats2half2_rn(v1.x, v1.y);
    __half2 h3 = __floats2half2_rn(v1.z, v1.w);
    uint4 o;
    o.x = *(uint32_t*)&h0; o.y = *(uint32_t*)&h1;
    o.z = *(uint32_t*)&h2; o.w = *(uint32_t*)&h3;
    dst[i] = o;
}

// ---------------- prologue kernels ----------------
__global__ void zero_counts_kernel() {
    if (threadIdx.x < NEXP) g_counts[threadIdx.x] = 0;
}

__global__ void gate_kernel(const float* __restrict__ x,
                            const float* __restrict__ Wg,
                            const float* __restrict__ bg) {
    int gwarp = (blockIdx.x * blockDim.x + threadIdx.x) >> 5;
    int lane  = threadIdx.x & 31;
    if (gwarp >= N_TOK) return;
    const float* xr = x + (size_t)gwarp * DIM;

    float acc[NEXP];
#pragma unroll
    for (int e = 0; e < NEXP; e++) acc[e] = 0.f;
    for (int d = lane; d < DIM; d += 32) {
        float xv = xr[d];
        const float* wr = Wg + d * NEXP;
#pragma unroll
        for (int e = 0; e < NEXP; e++) acc[e] += xv * wr[e];
    }
#pragma unroll
    for (int e = 0; e < NEXP; e++)
#pragma unroll
        for (int off = 16; off > 0; off >>= 1)
            acc[e] += __shfl_xor_sync(0xffffffffu, acc[e], off);
    if (lane == 0) {
        float lmax = -1e30f; int imax = 0;
#pragma unroll
        for (int e = 0; e < NEXP; e++) {
            float l = acc[e] + bg[e];
            acc[e] = l;
            if (l > lmax) { lmax = l; imax = e; }
        }
        float s = 0.f;
#pragma unroll
        for (int e = 0; e < NEXP; e++) s += expf(acc[e] - lmax);
        g_gate[gwarp] = 1.f / s;
        g_gidx[gwarp] = imax;
        atomicAdd(&g_counts[imax], 1);
    }
}

__global__ void prefix_kernel() {
    int s = 0;
    g_offsets[0] = 0;
    for (int e = 0; e < NEXP; e++) {
        g_cursor[e] = s;
        s += g_counts[e];
        g_offsets[e + 1] = s;
    }
}

__global__ void scatter_kernel() {
    int n = blockIdx.x * blockDim.x + threadIdx.x;
    if (n >= N_TOK) return;
    int e = g_gidx[n];
    int pos = atomicAdd(&g_cursor[e], 1);
    g_perm[pos] = n;
}

// ---------------- fp16 tensor-core GEMM -----------------------------------
// G2=false: h = relu(x_g @ W1[e] + b1[e]) -> g_hbufh (fp16)
// G2=true : out[tok] = gate * (h @ W2[e] + b2[e]) -> out (fp32)
// grid (NW/BN, N_TOK/BM, NEXP), block 256 (8 warps 4x2; warp tile 32x64)
template <int KT, int NW, bool G2>
__global__ __launch_bounds__(256, 2)
void moe_gemm_f16(const __half* __restrict__ Ah,   // g_xh (G1) / g_hbufh (G2)
                  const __half* __restrict__ Wh,
                  const float* __restrict__ bias,
                  float* __restrict__ outp) {
    constexpr int NIT = KT / BK;

    int e    = blockIdx.z;
    int off  = g_offsets[e];
    int ne   = g_offsets[e + 1] - off;
    int row0 = blockIdx.y * BM;
    if (row0 >= ne) return;
    int col0 = blockIdx.x * BN;

    extern __shared__ char smem[];
    uint32_t sb    = smem_u32(smem);
    int*     s_tok = (int*)smem;   // 128 ints

    int t    = threadIdx.x;
    int lane = t & 31;
    int wid  = t >> 5;
    int gr   = lane >> 2;
    int tg   = lane & 3;
    int wm   = (wid & 3) * 32;
    int wn   = (wid >> 2) * 64;

    if (t < BM) {
        int r = row0 + t;
        s_tok[t] = (r < ne) ? g_perm[off + r] : -1;
    }
    __syncthreads();

    // A cp mapping: 2 chunks/thread: c = t + p*256; row = c/4, kc = c%4 (8 halfs)
    const __half* asrc[2];
    uint32_t asz[2], adst[2];
#pragma unroll
    for (int p = 0; p < 2; p++) {
        int c   = t + p * 256;
        int row = c >> 2;
        int kc  = c & 3;
        bool ok;
        size_t ridx;
        if (!G2) {
            int tok = s_tok[row];
            ok   = (tok >= 0);
            ridx = (size_t)(ok ? tok : 0) * KT;
        } else {
            ok   = (row0 + row) < ne;
            ridx = (size_t)(ok ? (off + row0 + row) : 0) * KT;
        }
        asz[p]  = ok ? 16u : 0u;
        asrc[p] = Ah + ridx + kc * 8;
        adst[p] = (uint32_t)(row * SA + kc * 8) * 2;
    }
    // B cp mapping: 2 chunks/thread: c = t + p*256; krow = c/16, nc = c%16
    const __half* bsrc[2];
    uint32_t bdst[2];
#pragma unroll
    for (int p = 0; p < 2; p++) {
        int c    = t + p * 256;
        int krow = c >> 4;
        int nc   = c & 15;
        bsrc[p]  = Wh + (size_t)e * KT * NW + (size_t)krow * NW + col0 + nc * 8;
        bdst[p]  = (uint32_t)(krow * SB + nc * 8) * 2;
    }

    auto issue = [&](int it) {
        int buf = it & 1;
        uint32_t ab = sb + 512 + buf * ASZ;
        uint32_t bb = sb + 512 + 2 * ASZ + buf * BSZ;
        int k0 = it * BK;
#pragma unroll
        for (int p = 0; p < 2; p++)
            cp16(ab + adst[p], asrc[p] + k0, asz[p]);
#pragma unroll
        for (int p = 0; p < 2; p++)
            cp16(bb + bdst[p], bsrc[p] + (size_t)k0 * NW, 16u);
        cp_commit();
    };

    // ldmatrix base addresses (per-lane)
    // A: addr(mt,ks) = Ab + (wm + mt*16 + (lane&15))*SA*2 + (ks*16 + (lane>>4)*8)*2
    uint32_t aoff = (uint32_t)((wm + (lane & 15)) * SA + (lane >> 4) * 8) * 2;
    // B: addr(g,ks)  = Bb + (ks*16 + (lane&15))*SB*2 + (wn + g*16 + (lane>>4)*8)*2
    uint32_t boff = (uint32_t)((lane & 15) * SB + wn + (lane >> 4) * 8) * 2;

    float acc[2][8][4];
#pragma unroll
    for (int mt = 0; mt < 2; mt++)
#pragma unroll
        for (int nt = 0; nt < 8; nt++)
#pragma unroll
            for (int i = 0; i < 4; i++) acc[mt][nt][i] = 0.f;

    issue(0);
    for (int it = 0; it < NIT; it++) {
        cp_wait0();
        __syncthreads();
        if (it + 1 < NIT) issue(it + 1);

        int buf = it & 1;
        uint32_t Ab = sb + 512 + buf * ASZ + aoff;
        uint32_t Bb = sb + 512 + 2 * ASZ + buf * BSZ + boff;
#pragma unroll
        for (int ks = 0; ks < 2; ks++) {
            uint32_t a[2][4];
#pragma unroll
            for (int mt = 0; mt < 2; mt++)
                ldsm4(a[mt][0], a[mt][1], a[mt][2], a[mt][3],
                      Ab + (uint32_t)(mt * 16 * SA + ks * 16) * 2);
            uint32_t b[4][4];
#pragma unroll
            for (int g = 0; g < 4; g++)
                ldsm4t(b[g][0], b[g][1], b[g][2], b[g][3],
                       Bb + (uint32_t)(ks * 16 * SB + g * 16) * 2);
#pragma unroll
            for (int mt = 0; mt < 2; mt++)
#pragma unroll
                for (int g = 0; g < 4; g++) {
                    mma_f16(acc[mt][2 * g + 0], a[mt][0], a[mt][1], a[mt][2], a[mt][3],
                            b[g][0], b[g][1]);
                    mma_f16(acc[mt][2 * g + 1], a[mt][0], a[mt][1], a[mt][2], a[mt][3],
                            b[g][2], b[g][3]);
                }
        }
    }

    // -------- epilogue --------
    const float* be = bias + (size_t)e * NW;
#pragma unroll
    for (int mt = 0; mt < 2; mt++) {
#pragma unroll
        for (int half_ = 0; half_ < 2; half_++) {
            int rl = wm + mt * 16 + gr + half_ * 8;
            if (!G2) {
                if (row0 + rl >= ne) continue;
                __half* orow = g_hbufh + (size_t)(off + row0 + rl) * NW;
#pragma unroll
                for (int nt = 0; nt < 8; nt++) {
                    int col = col0 + wn + nt * 8 + tg * 2;
                    float2 bb = *(const float2*)(be + col);
                    __half2 h = __floats2half2_rn(
                        fmaxf(acc[mt][nt][half_ * 2 + 0] + bb.x, 0.f),
                        fmaxf(acc[mt][nt][half_ * 2 + 1] + bb.y, 0.f));
                    *(__half2*)(orow + col) = h;
                }
            } else {
                int tok = s_tok[rl];
                if (tok < 0) continue;
                float g = g_gate[tok];
                float* orow = outp + (size_t)tok * NW;
#pragma unroll
                for (int nt = 0; nt < 8; nt++) {
                    int col = col0 + wn + nt * 8 + tg * 2;
                    float2 bb = *(const float2*)(be + col);
                    float2 o;
                    o.x = g * (acc[mt][nt][half_ * 2 + 0] + bb.x);
                    o.y = g * (acc[mt][nt][half_ * 2 + 1] + bb.y);
                    *(float2*)(orow + col) = o;
                }
            }
        }
    }
}

// ---------------- launch ----------------
extern "C" void kernel_launch(void* const* d_in, const int* in_sizes, int n_in,
                              void* d_out, int out_size) {
    const float* x  = (const float*)d_in[0];
    const float* Wg = (const float*)d_in[1];
    const float* bg = (const float*)d_in[2];
    const float* W1 = (const float*)d_in[3];
    const float* b1 = (const float*)d_in[4];
    const float* W2 = (const float*)d_in[5];
    const float* b2 = (const float*)d_in[6];
    float* out = (float*)d_out;

    __half *w1h, *w2h, *xh;
    cudaGetSymbolAddress((void**)&w1h, g_w1h);
    cudaGetSymbolAddress((void**)&w2h, g_w2h);
    cudaGetSymbolAddress((void**)&xh, g_xh);

    // conversions (independent of gating)
    const int WN8 = NEXP * DIM * HID / 8;       // 5,898,240
    f32_to_f16_kernel<<<WN8 / 256, 256>>>((const float4*)W1, (uint4*)w1h, WN8);
    f32_to_f16_kernel<<<WN8 / 256, 256>>>((const float4*)W2, (uint4*)w2h, WN8);
    const int XN8 = N_TOK * DIM / 8;            // 393,216
    f32_to_f16_kernel<<<XN8 / 256, 256>>>((const float4*)x, (uint4*)xh, XN8);

    zero_counts_kernel<<<1, 32>>>();
    gate_kernel<<<(N_TOK * 32 + 255) / 256, 256>>>(x, Wg, bg);
    prefix_kernel<<<1, 1>>>();
    scatter_kernel<<<(N_TOK + 255) / 256, 256>>>();

    dim3 g1(HID / BN, N_TOK / BM, NEXP);
    moe_gemm_f16<DIM, HID, false><<<g1, 256, SMEM_TOT>>>(xh, w1h, b1, nullptr);

    dim3 g2(ODIM / BN, N_TOK / BM, NEXP);
    __half* hb;
    cudaGetSymbolAddress((void**)&hb, g_hbufh);
    moe_gemm_f16<HID, ODIM, true><<<g2, 256, SMEM_TOT>>>(hb, w2h, b2, out);
}